// round 16
// baseline (speedup 1.0000x reference)
#include <cuda_runtime.h>
#include <cuda_fp16.h>
#include <stdint.h>

#define BATCH   4096
#define IN_DIM  16384
#define OUT_DIM 16384
#define THREADS 1024
#define PAIRS   (BATCH / 2)       // 2048
#define NGROUP  8                 // compute groups (2 j per thread each)
#define CHUNK_COLS 4096           // columns per TMA chunk
#define CHUNK_BYTES (CHUNK_COLS * 4 * 2)   // 32KB (both rows' segment)
#define NCHUNK  (IN_DIM / CHUNK_COLS)      // 4
#define SLOT_BYTES (IN_DIM * 4)            // 64KB half2-interleaved

// Per-j k coefficients, 8B: x = half2(k0,k1), y = half2(k2,k3)
__device__ uint2    g_k8[OUT_DIM];
// Per-j packed indices: a | (b<<16)
__device__ uint32_t g_idx_pack[OUT_DIM];
// Dynamic work queue counter
__device__ int g_ctr;

__constant__ float c_gate[16][4] = {
    {0.f, 0.f, 0.f, 0.f}, {0.f, 0.f, 0.f, 1.f}, {0.f, 1.f, 0.f,-1.f}, {0.f, 1.f, 0.f, 0.f},
    {0.f, 0.f, 1.f,-1.f}, {0.f, 0.f, 1.f, 0.f}, {0.f, 1.f, 1.f,-2.f}, {0.f, 1.f, 1.f,-1.f},
    {1.f,-1.f,-1.f, 1.f}, {1.f,-1.f,-1.f, 2.f}, {1.f, 0.f,-1.f, 0.f}, {1.f, 0.f,-1.f, 1.f},
    {1.f,-1.f, 0.f, 0.f}, {1.f,-1.f, 0.f, 1.f}, {1.f, 0.f, 0.f,-1.f}, {1.f, 0.f, 0.f, 0.f}
};

// int64-vs-int32 buffer detection (R1 fix).
__device__ __forceinline__ bool idx_is_int64(const int* p) {
    bool odd_all_zero = true;
    #pragma unroll
    for (int i = 1; i < 64; i += 2) odd_all_zero &= (p[i] == 0);
    return odd_all_zero;
}
__device__ __forceinline__ int load_index(const void* base, int j, bool is64) {
    if (is64) return (int)((const long long*)base)[j];
    return ((const int*)base)[j];
}

__global__ void prep_kernel(const float* __restrict__ w,
                            const void* __restrict__ a_idx,
                            const void* __restrict__ b_idx,
                            int ncta)
{
    int j = blockIdx.x * blockDim.x + threadIdx.x;
    if (j == 0) g_ctr = ncta;   // first ncta pairs statically assigned
    if (j >= OUT_DIM) return;

    const bool a64 = idx_is_int64((const int*)a_idx);
    const bool b64 = idx_is_int64((const int*)b_idx);

    float wv[16];
    const float4* w4 = reinterpret_cast<const float4*>(w + (size_t)j * 16);
    #pragma unroll
    for (int q = 0; q < 4; q++) {
        float4 v = __ldg(&w4[q]);
        wv[q*4+0] = v.x; wv[q*4+1] = v.y; wv[q*4+2] = v.z; wv[q*4+3] = v.w;
    }
    float m = wv[0];
    #pragma unroll
    for (int i = 1; i < 16; i++) m = fmaxf(m, wv[i]);
    float e[16], s = 0.f;
    #pragma unroll
    for (int i = 0; i < 16; i++) { e[i] = __expf(wv[i] - m); s += e[i]; }
    float inv = 1.0f / s;

    float k0 = 0.f, k1 = 0.f, k2 = 0.f, k3 = 0.f;
    #pragma unroll
    for (int i = 0; i < 16; i++) {
        float p = e[i] * inv;
        k0 = fmaf(p, c_gate[i][0], k0);
        k1 = fmaf(p, c_gate[i][1], k1);
        k2 = fmaf(p, c_gate[i][2], k2);
        k3 = fmaf(p, c_gate[i][3], k3);
    }

    unsigned int ia = (unsigned int)load_index(a_idx, j, a64);
    unsigned int ib = (unsigned int)load_index(b_idx, j, b64);

    __half2 h01 = __floats2half2_rn(k0, k1);
    __half2 h23 = __floats2half2_rn(k2, k3);
    uint2 k8;
    k8.x = *reinterpret_cast<unsigned int*>(&h01);
    k8.y = *reinterpret_cast<unsigned int*>(&h23);
    g_k8[j] = k8;
    g_idx_pack[j] = ia | (ib << 16);
}

// ---- mbarrier / TMA-bulk helpers ----
__device__ __forceinline__ uint32_t smem_u32(const void* p) {
    uint32_t a;
    asm("{ .reg .u64 t; cvta.to.shared.u64 t, %1; cvt.u32.u64 %0, t; }" : "=r"(a) : "l"(p));
    return a;
}
__device__ __forceinline__ void mbar_init(uint32_t mbar, uint32_t cnt) {
    asm volatile("mbarrier.init.shared.b64 [%0], %1;" :: "r"(mbar), "r"(cnt) : "memory");
}
__device__ __forceinline__ void mbar_expect_tx(uint32_t mbar, uint32_t bytes) {
    asm volatile("mbarrier.arrive.expect_tx.shared.b64 _, [%0], %1;"
                 :: "r"(mbar), "r"(bytes) : "memory");
}
__device__ __forceinline__ void mbar_arrive(uint32_t mbar) {
    asm volatile("mbarrier.arrive.shared.b64 _, [%0];" :: "r"(mbar) : "memory");
}
__device__ __forceinline__ void mbar_wait(uint32_t mbar, uint32_t phase) {
    asm volatile(
        "{\n\t.reg .pred P;\n\t"
        "WL_%=:\n\t"
        "mbarrier.try_wait.parity.acquire.cta.shared::cta.b64 P, [%0], %1, 0x989680;\n\t"
        "@P bra.uni WD_%=;\n\t"
        "bra.uni WL_%=;\n\t"
        "WD_%=:\n\t}"
        :: "r"(mbar), "r"(phase) : "memory");
}
__device__ __forceinline__ void bulk_g2s(uint32_t dst, const void* src, uint32_t bytes, uint32_t mbar) {
    asm volatile(
        "cp.async.bulk.shared::cta.global.mbarrier::complete_tx::bytes [%0], [%1], %2, [%3];"
        :: "r"(dst), "l"(src), "r"(bytes), "r"(mbar) : "memory");
}
__device__ __forceinline__ void fence_proxy_async() {
    asm volatile("fence.proxy.async.shared::cta;" ::: "memory");
}

// Issue TMA for chunk c of pair p into ring slot (addr ringa, full-barrier mbar).
__device__ __forceinline__ void issue_chunk(const float* x, int p, int c,
                                            uint32_t ringa, uint32_t mbar)
{
    const float* src = x + (size_t)(2 * p) * IN_DIM + c * CHUNK_COLS;
    mbar_expect_tx(mbar, CHUNK_BYTES);
    bulk_g2s(ringa,                  src,          CHUNK_COLS * 4, mbar); // row even seg
    bulk_g2s(ringa + CHUNK_COLS * 4, src + IN_DIM, CHUNK_COLS * 4, mbar); // row odd seg
}

// Convert ring chunk c into the half2-interleaved slot. 1024 threads, one
// float4 per row each: 2 LDS.128 + cvt + 1 STS.128 per thread.
__device__ __forceinline__ void convert_chunk(const float4* __restrict__ ring,
                                              __half2* __restrict__ dst,
                                              int c, int tid)
{
    float4 e = ring[tid];                      // row even
    float4 o = ring[(CHUNK_COLS / 4) + tid];   // row odd
    __half2 h0 = __floats2half2_rn(e.x, o.x);
    __half2 h1 = __floats2half2_rn(e.y, o.y);
    __half2 h2 = __floats2half2_rn(e.z, o.z);
    __half2 h3 = __floats2half2_rn(e.w, o.w);
    uint4 pk;
    pk.x = *reinterpret_cast<unsigned int*>(&h0);
    pk.y = *reinterpret_cast<unsigned int*>(&h1);
    pk.z = *reinterpret_cast<unsigned int*>(&h2);
    pk.w = *reinterpret_cast<unsigned int*>(&h3);
    *reinterpret_cast<uint4*>(dst + c * CHUNK_COLS + 4 * tid) = pk;
}

// Evaluate one j for both rows of the pair.
__device__ __forceinline__ void eval2(uint32_t idxp, uint32_t k01u, uint32_t k23u,
                                      const __half2* __restrict__ xs,
                                      float& ve, float& vo)
{
    float2 k01 = __half22float2(*reinterpret_cast<__half2*>(&k01u));
    float2 k23 = __half22float2(*reinterpret_cast<__half2*>(&k23u));
    float2 a = __half22float2(xs[idxp & 0xFFFFu]);
    float2 b = __half22float2(xs[idxp >> 16]);
    ve = fmaf(a.x, fmaf(k23.y, b.x, k01.y), fmaf(k23.x, b.x, k01.x));
    vo = fmaf(a.y, fmaf(k23.y, b.y, k01.y), fmaf(k23.x, b.y, k01.x));
}

// One compute group: 2 consecutive j for both rows.
__device__ __forceinline__ void compute_group(int g, int tid,
                                              const __half2* __restrict__ xs,
                                              float* __restrict__ oe,
                                              float* __restrict__ oo)
{
    const int j0 = g * (OUT_DIM / NGROUP) + tid * 2;
    uint2 I = __ldg(reinterpret_cast<const uint2*>(&g_idx_pack[j0]));
    uint4 K = __ldg(reinterpret_cast<const uint4*>(&g_k8[j0]));
    float2 ve, vo;
    eval2(I.x, K.x, K.y, xs, ve.x, vo.x);
    eval2(I.y, K.z, K.w, xs, ve.y, vo.y);
    __stcs(reinterpret_cast<float2*>(&oe[j0]), ve);
    __stcs(reinterpret_cast<float2*>(&oo[j0]), vo);
}

// TMA-streamed pipeline, 1 CTA/SM, 1024 threads.
// smem: two 64KB half2 slots + 2x32KB TMA chunk ring + mbarriers.
// Per pair: between compute groups 2c and 2c+1 of pair `comp` (slot[s]),
// ALL threads convert arriving chunk c of pair `fill` into slot[s^1]
// (wait full-mbar, convert, arrive drain-mbar), thread0 reissues the ring
// slot (crossing into pair `nxtf`). TMA streams across pair boundaries;
// convert has no exclusive window; one __syncthreads per pair.
__global__ void __launch_bounds__(THREADS, 1)
logic_main_kernel(const float* __restrict__ x, float* __restrict__ out)
{
    extern __shared__ __align__(16) unsigned char smem_raw[];
    __half2* slot[2] = {
        reinterpret_cast<__half2*>(smem_raw),
        reinterpret_cast<__half2*>(smem_raw + SLOT_BYTES)
    };
    const float4* ring4[2] = {
        reinterpret_cast<const float4*>(smem_raw + 2 * SLOT_BYTES),
        reinterpret_cast<const float4*>(smem_raw + 2 * SLOT_BYTES + CHUNK_BYTES)
    };
    uint32_t ring_a[2], mb_full[2], mb_drain[2];
    ring_a[0]  = smem_u32(smem_raw + 2 * SLOT_BYTES);
    ring_a[1]  = ring_a[0] + CHUNK_BYTES;
    mb_full[0] = smem_u32(smem_raw + 2 * SLOT_BYTES + 2 * CHUNK_BYTES);
    mb_full[1] = mb_full[0] + 8;
    mb_drain[0] = mb_full[0] + 16;
    mb_drain[1] = mb_full[0] + 24;
    __shared__ int s_pop[2];

    const int tid = threadIdx.x;

    if (tid == 0) {
        mbar_init(mb_full[0], 1);
        mbar_init(mb_full[1], 1);
        mbar_init(mb_drain[0], THREADS);
        mbar_init(mb_drain[1], THREADS);
        fence_proxy_async();
    }
    __syncthreads();

    uint32_t nf0 = 0, nf1 = 0;   // full-barrier wait phases (all threads)
    uint32_t nd0 = 0, nd1 = 0;   // drain-barrier wait phases (thread0)

    int fill = blockIdx.x;
    if (tid == 0) {
        issue_chunk(x, fill, 0, ring_a[0], mb_full[0]);
        issue_chunk(x, fill, 1, ring_a[1], mb_full[1]);
        s_pop[0] = atomicAdd(&g_ctr, 1);
    }
    __syncthreads();
    int nxtf = s_pop[0];

    // Prologue: convert all 4 chunks of `fill` into slot[0], reissuing the
    // ring (chunks 2,3 of fill, then chunks 0,1 of nxtf).
    #pragma unroll
    for (int c = 0; c < NCHUNK; c++) {
        const int r = c & 1;
        uint32_t& nf = r ? nf1 : nf0;
        mbar_wait(mb_full[r], nf & 1); nf++;
        convert_chunk(ring4[r], slot[0], c, tid);
        mbar_arrive(mb_drain[r]);
        if (tid == 0) {
            uint32_t& nd = r ? nd1 : nd0;
            mbar_wait(mb_drain[r], nd & 1); nd++;
            const int ip = (c < 2) ? fill : nxtf;
            const int ic = (c < 2) ? c + 2 : c - 2;
            if (ip < PAIRS) { fence_proxy_async(); issue_chunk(x, ip, ic, ring_a[r], mb_full[r]); }
        }
    }
    if (tid == 0) s_pop[1] = atomicAdd(&g_ctr, 1);
    __syncthreads();

    int comp = fill;       // pair in slot[s], ready
    fill = nxtf;           // pair streaming into slot[s^1]
    nxtf = s_pop[1];
    int s = 0, pi = 0;     // next pop written to s_pop[pi], read after sync

    while (comp < PAIRS) {
        const bool vfill = (fill < PAIRS);
        const __half2* __restrict__ xs = slot[s];
        float* __restrict__ oe = out + (size_t)(2 * comp) * OUT_DIM;
        float* __restrict__ oo = oe + OUT_DIM;

        #pragma unroll
        for (int c = 0; c < NCHUNK; c++) {
            compute_group(2 * c, tid, xs, oe, oo);

            if (vfill) {
                const int r = c & 1;
                uint32_t& nf = r ? nf1 : nf0;
                mbar_wait(mb_full[r], nf & 1); nf++;
                convert_chunk(ring4[r], slot[s ^ 1], c, tid);
                mbar_arrive(mb_drain[r]);
                if (tid == 0) {
                    uint32_t& nd = r ? nd1 : nd0;
                    mbar_wait(mb_drain[r], nd & 1); nd++;
                    const int ip = (c < 2) ? fill : nxtf;
                    const int ic = (c < 2) ? c + 2 : c - 2;
                    if (ip < PAIRS) { fence_proxy_async(); issue_chunk(x, ip, ic, ring_a[r], mb_full[r]); }
                }
            }

            compute_group(2 * c + 1, tid, xs, oe, oo);
        }

        if (tid == 0) s_pop[pi] = atomicAdd(&g_ctr, 1);
        __syncthreads();   // slot[s^1] complete, slot[s] free, pop visible

        comp = fill;
        fill = nxtf;
        nxtf = s_pop[pi];
        pi ^= 1;
        s ^= 1;
    }
}

extern "C" void kernel_launch(void* const* d_in, const int* in_sizes, int n_in,
                              void* d_out, int out_size)
{
    const float* x  = (const float*)d_in[0];
    const float* w  = (const float*)d_in[1];
    const void*  ai = d_in[2];
    const void*  bi = d_in[3];
    float* out = (float*)d_out;
    (void)in_sizes; (void)n_in; (void)out_size;

    int nsm = 148;
    cudaDeviceGetAttribute(&nsm, cudaDevAttrMultiProcessorCount, 0);
    const int ncta = nsm;   // 1 CTA per SM

    // 2x64KB slots + 2x32KB ring + mbarriers
    const int smem_bytes = 2 * SLOT_BYTES + 2 * CHUNK_BYTES + 64;
    cudaFuncSetAttribute(logic_main_kernel,
                         cudaFuncAttributeMaxDynamicSharedMemorySize, smem_bytes);

    prep_kernel<<<(OUT_DIM + 511) / 512, 512>>>(w, ai, bi, ncta);
    logic_main_kernel<<<ncta, THREADS, smem_bytes>>>(x, out);
}